// round 17
// baseline (speedup 1.0000x reference)
#include <cuda_runtime.h>
#include <cuda_bf16.h>
#include <cstdint>

// ---------------------------------------------------------------------------
// manyToManyGRU: B=32, T=128, DIN=DOUT=1024, fp32.
//
// R16 vs R15 (867us): schedule-only changes, numerics identical.
//   - z-gate moved from phase A into phase B *before* the rh poll: its mma
//     and partial stores execute inside the rh round-trip shadow. Phase A is
//     r-only (16 mma/warp, 16-LDS reduce). Requires parity double-buffered h
//     (g_hA[2]) to close the WAR between B(t)'s z-mma reads of h_{t-1} and a
//     fast producer's h_t publication (safe by induction via A(t+1)'s sync).
//   - spar split into 3 disjoint regions (r/z/hhat): each phase's mandatory
//     store->read __syncthreads also covers the other phase's WAR -> the 2
//     WAR-only __syncthreads per step are deleted.
//   - h_prev lives in a register (same thread does both reduces now);
//     sh_z / sh_h smem removed.
// ---------------------------------------------------------------------------

#define B_   32
#define T_   128
#define D_   1024
#define NCTA 64
#define JPC  16
#define TPB  512
#define NW   16
#define NGRP 8
#define GRPSZ 8

// gx layout: [(g*T + t)*B + b]*D + j
__device__ __align__(16) float g_gx[(size_t)3*T_*B_*D_];
// h broadcast planes (bf16-hi, fragment-linear), parity double-buffered;
// rh single buffer (WAR closed by flagH gating as before)
__device__ __align__(16) uint32_t g_hA[2][NW*1024];
__device__ __align__(16) uint32_t g_rA[NW*1024];
__device__ __align__(128) unsigned g_bar_cnt[NGRP*32];
__device__ unsigned g_bar_root = 0;
__device__ unsigned g_bar_gen  = 0;
// per-CTA monotone phase counters (128B padded); 16 warp-arrivals per phase
__device__ __align__(128) unsigned g_flagH[NCTA*32];
__device__ __align__(128) unsigned g_flagR[NCTA*32];

// bf16 split planes
__device__ __align__(16) __nv_bfloat16 g_Wb[2][(size_t)3*D_*D_];  // [(g*1024+j)*1024+k]
__device__ __align__(16) __nv_bfloat16 g_Ub[2][(size_t)3*D_*D_];  // [(g*1024+j)*1024+k]
__device__ __align__(16) __nv_bfloat16 g_xb[2][(size_t)B_*T_*D_]; // [(b*T+t)*1024+k]

__device__ __forceinline__ float sigm(float v) { return 1.0f / (1.0f + __expf(-v)); }

__device__ __forceinline__ uint32_t smem_to_u32(const void* p) {
    uint32_t a;
    asm("{ .reg .u64 t; cvta.to.shared.u64 t, %1; cvt.u32.u64 %0, t; }"
        : "=r"(a) : "l"(p));
    return a;
}
__device__ __forceinline__ void ldsm4(uint32_t* r, uint32_t a) {
    asm volatile("ldmatrix.sync.aligned.m8n8.x4.shared.b16 {%0,%1,%2,%3}, [%4];"
        : "=r"(r[0]), "=r"(r[1]), "=r"(r[2]), "=r"(r[3]) : "r"(a));
}
__device__ __forceinline__ void ldsm2(uint32_t* r, uint32_t a) {
    asm volatile("ldmatrix.sync.aligned.m8n8.x2.shared.b16 {%0,%1}, [%2];"
        : "=r"(r[0]), "=r"(r[1]) : "r"(a));
}
__device__ __forceinline__ void mma16816(float* c, const uint32_t* a, const uint32_t* b) {
    asm volatile("mma.sync.aligned.m16n8k16.row.col.f32.bf16.bf16.f32 "
        "{%0,%1,%2,%3}, {%4,%5,%6,%7}, {%8,%9}, {%0,%1,%2,%3};"
        : "+f"(c[0]), "+f"(c[1]), "+f"(c[2]), "+f"(c[3])
        : "r"(a[0]), "r"(a[1]), "r"(a[2]), "r"(a[3]), "r"(b[0]), "r"(b[1]));
}

// memory-order primitives
__device__ __forceinline__ unsigned ld_acq(const unsigned* p) {
    unsigned v;
    asm volatile("ld.acquire.gpu.global.u32 %0, [%1];" : "=r"(v) : "l"(p) : "memory");
    return v;
}
__device__ __forceinline__ unsigned atom_inc_acqrel(unsigned* p) {
    unsigned o;
    asm volatile("atom.acq_rel.gpu.global.add.u32 %0, [%1], 1;" : "=r"(o) : "l"(p) : "memory");
    return o;
}
__device__ __forceinline__ void st_rlx(unsigned* p, unsigned v) {
    asm volatile("st.relaxed.gpu.global.u32 [%0], %1;" :: "l"(p), "r"(v) : "memory");
}
__device__ __forceinline__ void red_add_rel(unsigned* p, unsigned v) {
    asm volatile("red.release.gpu.global.add.u32 [%0], %1;" :: "l"(p), "r"(v) : "memory");
}

// ===================== kernel 1: fused fp32 -> bf16 (hi,lo) split ==========
__global__ void split_all(const float* __restrict__ Wz, const float* __restrict__ Wr,
                          const float* __restrict__ Wh, const float* __restrict__ Uz,
                          const float* __restrict__ Ur, const float* __restrict__ Uh,
                          const float* __restrict__ x)
{
    const int M4  = (D_*D_) / 4;
    const int NX4 = (B_*T_*D_) / 4;
    const int tot = 6*M4 + NX4;
    for (int i = blockIdx.x*blockDim.x + threadIdx.x; i < tot;
         i += gridDim.x*blockDim.x) {
        float4 v;
        int mat, off;
        if (i < 6*M4) {
            mat = i / M4; off = i - mat*M4;
            const float* src = (mat==0)?Wz:(mat==1)?Wr:(mat==2)?Wh:
                               (mat==3)?Uz:(mat==4)?Ur:Uh;
            v = __ldg((const float4*)src + off);
        } else {
            mat = 7; off = i - 6*M4;
            v = __ldg((const float4*)x + off);
        }
        __nv_bfloat16 h0 = __float2bfloat16(v.x), h1 = __float2bfloat16(v.y);
        __nv_bfloat16 h2 = __float2bfloat16(v.z), h3 = __float2bfloat16(v.w);
        __nv_bfloat16 l0 = __float2bfloat16(v.x - __bfloat162float(h0));
        __nv_bfloat16 l1 = __float2bfloat16(v.y - __bfloat162float(h1));
        __nv_bfloat16 l2 = __float2bfloat16(v.z - __bfloat162float(h2));
        __nv_bfloat16 l3 = __float2bfloat16(v.w - __bfloat162float(h3));
        uint2 hp, lp;
        hp.x = ((uint32_t)__bfloat16_as_ushort(h1) << 16) | __bfloat16_as_ushort(h0);
        hp.y = ((uint32_t)__bfloat16_as_ushort(h3) << 16) | __bfloat16_as_ushort(h2);
        lp.x = ((uint32_t)__bfloat16_as_ushort(l1) << 16) | __bfloat16_as_ushort(l0);
        lp.y = ((uint32_t)__bfloat16_as_ushort(l3) << 16) | __bfloat16_as_ushort(l2);
        if (mat < 3) {
            *(uint2*)&g_Wb[0][(size_t)mat*D_*D_ + (size_t)off*4] = hp;
            *(uint2*)&g_Wb[1][(size_t)mat*D_*D_ + (size_t)off*4] = lp;
        } else if (mat < 6) {
            *(uint2*)&g_Ub[0][(size_t)(mat-3)*D_*D_ + (size_t)off*4] = hp;
            *(uint2*)&g_Ub[1][(size_t)(mat-3)*D_*D_ + (size_t)off*4] = lp;
        } else {
            *(uint2*)&g_xb[0][(size_t)off*4] = hp;
            *(uint2*)&g_xb[1][(size_t)off*4] = lp;
        }
    }
}

// ===================== kernel 2: mma.sync GEMM for gx ======================
// 3 staged planes (Ahi, Bhi, Blo); products: Ahi*Bhi + Ahi*Blo.
#define GM_THREADS 256
#define ASTRIDE 40
#define PLANE   (128*ASTRIDE)
#define GEMM_SMEM (3*PLANE*2)

__global__ void __launch_bounds__(GM_THREADS, 2)
gemm_kernel(const float* __restrict__ bz, const float* __restrict__ cz,
            const float* __restrict__ br, const float* __restrict__ cr,
            const float* __restrict__ bh, const float* __restrict__ ch)
{
    extern __shared__ __nv_bfloat16 sm[];
    const int tid  = threadIdx.x;
    const int w    = tid >> 5;
    const int lane = tid & 31;
    const int wm   = w >> 2;
    const int wn   = w & 3;
    const int mbase = blockIdx.y * 128;
    const int nbase = blockIdx.x * 128;
    const uint32_t smb = smem_to_u32(sm);

    float acc[4][4][4];
    #pragma unroll
    for (int mf = 0; mf < 4; mf++)
        #pragma unroll
        for (int nf = 0; nf < 4; nf++)
            #pragma unroll
            for (int i = 0; i < 4; i++) acc[mf][nf][i] = 0.0f;

    for (int kc = 0; kc < 32; kc++) {
        #pragma unroll
        for (int it = 0; it < 6; it++) {
            const int idx  = tid + it * GM_THREADS;    // < 1536
            const int part = idx >> 9;                 // 0 Ahi, 1 Bhi, 2 Blo
            const int rem  = idx & 511;
            const int row  = rem >> 2;
            const int chk  = rem & 3;
            const uint4* src = (part == 0)
                ? (const uint4*)&g_Wb[0][((size_t)(mbase + row) << 10) + kc*32 + chk*8]
                : (const uint4*)&g_xb[part - 1][((size_t)(nbase + row) << 10) + kc*32 + chk*8];
            *(uint4*)&sm[part*PLANE + row*ASTRIDE + chk*8] = __ldg(src);
        }
        __syncthreads();

        #pragma unroll
        for (int h = 0; h < 2; h++) {
            const int k16 = h * 16;
            uint32_t af[4][4], bhf[4][2], blf[4][2];
            #pragma unroll
            for (int mf = 0; mf < 4; mf++) {
                const uint32_t a = smb + 2u*(0*PLANE +
                    (wm*64 + mf*16 + (lane & 15))*ASTRIDE + k16 + (lane >> 4)*8);
                ldsm4(af[mf], a);
            }
            #pragma unroll
            for (int nf = 0; nf < 4; nf++) {
                const uint32_t rc = (wn*32 + nf*8 + (lane & 7))*ASTRIDE + k16 + ((lane >> 3) & 1)*8;
                ldsm2(bhf[nf], smb + 2u*(1*PLANE + rc));
                ldsm2(blf[nf], smb + 2u*(2*PLANE + rc));
            }
            #pragma unroll
            for (int mf = 0; mf < 4; mf++)
                #pragma unroll
                for (int nf = 0; nf < 4; nf++) {
                    mma16816(acc[mf][nf], af[mf], bhf[nf]);
                    mma16816(acc[mf][nf], af[mf], blf[nf]);
                }
        }
        __syncthreads();
    }

    const int g = mbase >> 10;
    const float* bp = (g == 0) ? bz : (g == 1) ? br : bh;
    const float* cp = (g == 0) ? cz : (g == 1) ? cr : ch;
    #pragma unroll
    for (int mf = 0; mf < 4; mf++) {
        const int row0 = wm*64 + mf*16 + (lane >> 2);
        const int jl0  = (mbase + row0) & 1023;
        const int jl8  = (mbase + row0 + 8) & 1023;
        const float bias0 = bp[jl0] + cp[jl0];
        const float bias8 = bp[jl8] + cp[jl8];
        #pragma unroll
        for (int nf = 0; nf < 4; nf++) {
            const int col0 = wn*32 + nf*8 + (lane & 3)*2;
            #pragma unroll
            for (int cc = 0; cc < 2; cc++) {
                const int n = nbase + col0 + cc;
                const int b = n >> 7;
                const int t = n & 127;
                const size_t base = ((size_t)(g*T_ + t)*B_ + b)*D_;
                g_gx[base + jl0] = acc[mf][nf][cc]     + bias0;
                g_gx[base + jl8] = acc[mf][nf][cc + 2] + bias8;
            }
        }
    }
}

// ===================== kernel 3: persistent recurrence =====================
__device__ __forceinline__ void grid_barrier(int grp)
{
    __syncthreads();
    if (threadIdx.x == 0) {
        const unsigned gen = ld_acq(&g_bar_gen);
        if (atom_inc_acqrel(&g_bar_cnt[grp*32]) == GRPSZ - 1u) {
            st_rlx(&g_bar_cnt[grp*32], 0u);
            if (atom_inc_acqrel(&g_bar_root) == NGRP - 1u) {
                st_rlx(&g_bar_root, 0u);
                atom_inc_acqrel(&g_bar_gen);
            } else {
                while (ld_acq(&g_bar_gen) == gen) { }
            }
        } else {
            while (ld_acq(&g_bar_gen) == gen) { }
        }
    }
    __syncthreads();
}

#define UHSTRIDE 1032                      // bf16 elems; pad -> conflict-free LDS
#define UHP (JPC*UHSTRIDE)                 // elems per plane
#define SPARSZ (NW*512)                    // floats per spar region
#define GRU_SMEM (3*SPARSZ*4 + 2*UHP*2)    // 96KB partials + 66048B Uh

__global__ void __launch_bounds__(TPB, 1)
gru_kernel(float* __restrict__ out)
{
    extern __shared__ char dyn[];
    float* spar_r = (float*)dyn;                         // [NW][512]
    float* spar_z = (float*)(dyn + 1*SPARSZ*4);          // [NW][512]
    float* spar_h = (float*)(dyn + 2*SPARSZ*4);          // [NW][512]
    __nv_bfloat16* shUh = (__nv_bfloat16*)(dyn + 3*SPARSZ*4);  // [2][JPC][1032]

    const int tid  = threadIdx.x;
    const int w    = tid >> 5;
    const int lane = tid & 31;
    const int cta  = blockIdx.x;
    const int j0   = cta * JPC;
    const int grp  = cta >> 3;
    const int gid  = lane >> 2;
    const int tig  = lane & 3;

    // ---- stage Uh (hi,lo) rows j0..j0+15 into padded SMEM
    for (int i = tid; i < 2*JPC*512; i += TPB) {     // u32 units
        const int plane = i >> 13;                   // JPC*512 = 8192
        const int rem   = i & 8191;
        const int row   = rem >> 9;
        const int k2    = rem & 511;
        const uint32_t v = *(const uint32_t*)
            &g_Ub[plane][((size_t)(2*1024 + j0 + row) << 10) + (k2 << 1)];
        *(uint32_t*)&shUh[plane*UHP + row*UHSTRIDE + (k2 << 1)] = v;
    }

    // ---- preload Uz, Ur B-fragments (hi plane only) into registers
    uint32_t buz[4][2][2], bur[4][2][2];
    #pragma unroll
    for (int nf = 0; nf < 2; nf++) {
        const int jrow = j0 + nf*8 + gid;
        #pragma unroll
        for (int kt = 0; kt < 4; kt++) {
            const int k0 = (w << 6) + (kt << 4) + (tig << 1);
            const size_t rz = ((size_t)(0*1024 + jrow) << 10) + k0;
            const size_t rr = ((size_t)(1*1024 + jrow) << 10) + k0;
            buz[kt][nf][0] = *(const uint32_t*)&g_Ub[0][rz];
            buz[kt][nf][1] = *(const uint32_t*)&g_Ub[0][rz + 8];
            bur[kt][nf][0] = *(const uint32_t*)&g_Ub[0][rr];
            bur[kt][nf][1] = *(const uint32_t*)&g_Ub[0][rr + 8];
        }
    }

    // ---- per-thread (b, j) identity + packed-store targets
    const int rb  = tid >> 4;          // batch 0..31
    const int rjj = tid & 15;          // j within CTA slice
    const int rj  = j0 + rjj;
    const uint32_t sidx = (uint32_t)((cta >> 2)*1024
                        + (((cta & 3)*2 + (rb >> 4))*128)
                        + (((rb & 7)*4 + ((rjj >> 1) & 3))*4)
                        + ((rb >> 3) & 1) + ((rjj >> 3) << 1));
    uint32_t* hDst0 = &g_hA[0][sidx];
    uint32_t* hDst1 = &g_hA[1][sidx];
    uint32_t* rDst  = &g_rA[sidx];
    const bool packer = !(tid & 1);

    // ---- publish h0 = 0 into parity buffer 1 (read by t=0's phase A)
    if (packer) *hDst1 = 0u;
    __syncwarp();
    if (lane == 0) red_add_rel(&g_flagH[cta*32], 1u);   // counter -> 16

    const uint32_t abase = (w << 10) + (lane << 2);
    const unsigned* myFH = &g_flagH[((w << 2) + (lane & 3)) * 32];
    const unsigned* myFR = &g_flagR[((w << 2) + (lane & 3)) * 32];
    const bool poller = (lane < 4);

    float hprev = 0.0f;                // per-thread fp32 h(b,j)

    for (int t = 0; t < T_; t++) {
        const float gxZ = g_gx[((size_t)(0*T_ + t)*B_ + rb)*D_ + rj];
        const float gxR = g_gx[((size_t)(1*T_ + t)*B_ + rb)*D_ + rj];
        const float gxH = g_gx[((size_t)(2*T_ + t)*B_ + rb)*D_ + rj];
        const uint32_t* hbR = (t & 1) ? g_hA[0] : g_hA[1];   // holds h_{t-1}
        uint32_t*       hW  = (t & 1) ? hDst1   : hDst0;     // target for h_t

        // ================= phase A: r only =================
        if (poller) { const unsigned tgt = 16u*(unsigned)(t + 1);
                      while (ld_acq(myFH) < tgt) { } }
        __syncwarp();

        #pragma unroll
        for (int mt = 0; mt < 2; mt++) {
            float cr[2][4];
            #pragma unroll
            for (int nf = 0; nf < 2; nf++)
                #pragma unroll
                for (int i = 0; i < 4; i++) cr[nf][i] = 0.0f;

            uint4 af[4];
            #pragma unroll
            for (int kt = 0; kt < 4; kt++)
                af[kt] = __ldcg((const uint4*)(hbR + abase + ((kt*2 + mt) << 7)));
            #pragma unroll
            for (int kt = 0; kt < 4; kt++)
                #pragma unroll
                for (int nf = 0; nf < 2; nf++)
                    mma16816(cr[nf], (const uint32_t*)&af[kt], bur[kt][nf]);
            const int b0 = mt*16 + gid;
            #pragma unroll
            for (int nf = 0; nf < 2; nf++) {
                const int i0 = b0*16 + nf*8 + tig*2;
                *(float2*)&spar_r[w*512 + i0]       = make_float2(cr[nf][0], cr[nf][1]);
                *(float2*)&spar_r[w*512 + i0 + 128] = make_float2(cr[nf][2], cr[nf][3]);
            }
        }
        __syncthreads();                       // spar_r store -> read
        {
            float sr = gxR;
            #pragma unroll
            for (int w2 = 0; w2 < NW; w2++) sr += spar_r[w2*512 + tid];
            const float r  = sigm(sr);
            const float rh = r * hprev;
            const uint32_t v = (uint32_t)__bfloat16_as_ushort(__float2bfloat16(rh));
            const uint32_t p = __shfl_xor_sync(0xFFFFFFFFu, v, 1);
            if (packer) *rDst = v | (p << 16);
        }
        __syncwarp();
        if (lane == 0) red_add_rel(&g_flagR[cta*32], 1u);

        // ================= phase B: z (pre-poll) + candidate + update ======
        // z-mma on h_{t-1} executes inside the rh round-trip shadow
        #pragma unroll
        for (int mt = 0; mt < 2; mt++) {
            float czacc[2][4];
            #pragma unroll
            for (int nf = 0; nf < 2; nf++)
                #pragma unroll
                for (int i = 0; i < 4; i++) czacc[nf][i] = 0.0f;

            uint4 af[4];
            #pragma unroll
            for (int kt = 0; kt < 4; kt++)
                af[kt] = __ldcg((const uint4*)(hbR + abase + ((kt*2 + mt) << 7)));
            #pragma unroll
            for (int kt = 0; kt < 4; kt++)
                #pragma unroll
                for (int nf = 0; nf < 2; nf++)
                    mma16816(czacc[nf], (const uint32_t*)&af[kt], buz[kt][nf]);
            const int b0 = mt*16 + gid;
            #pragma unroll
            for (int nf = 0; nf < 2; nf++) {
                const int i0 = b0*16 + nf*8 + tig*2;
                *(float2*)&spar_z[w*512 + i0]       = make_float2(czacc[nf][0], czacc[nf][1]);
                *(float2*)&spar_z[w*512 + i0 + 128] = make_float2(czacc[nf][2], czacc[nf][3]);
            }
        }

        if (poller) { const unsigned tgt = 16u*(unsigned)(t + 1);
                      while (ld_acq(myFR) < tgt) { } }
        __syncwarp();

        #pragma unroll
        for (int mt = 0; mt < 2; mt++) {
            float ch[2][4];
            #pragma unroll
            for (int nf = 0; nf < 2; nf++)
                #pragma unroll
                for (int i = 0; i < 4; i++) ch[nf][i] = 0.0f;

            uint4 af[4];
            #pragma unroll
            for (int kt = 0; kt < 4; kt++)
                af[kt] = __ldcg((const uint4*)(g_rA + abase + ((kt*2 + mt) << 7)));
            #pragma unroll
            for (int kt = 0; kt < 4; kt++) {
                const int kcol = (w << 6) + (kt << 4) + (tig << 1);
                #pragma unroll
                for (int nf = 0; nf < 2; nf++) {
                    const __nv_bfloat16* bp = shUh + (nf*8 + gid)*UHSTRIDE + kcol;
                    uint32_t bh[2], bl[2];
                    bh[0] = *(const uint32_t*)bp;
                    bh[1] = *(const uint32_t*)(bp + 8);
                    bl[0] = *(const uint32_t*)(bp + UHP);
                    bl[1] = *(const uint32_t*)(bp + UHP + 8);
                    mma16816(ch[nf], (const uint32_t*)&af[kt], bh);
                    mma16816(ch[nf], (const uint32_t*)&af[kt], bl);
                }
            }
            const int b0 = mt*16 + gid;
            #pragma unroll
            for (int nf = 0; nf < 2; nf++) {
                const int i0 = b0*16 + nf*8 + tig*2;
                *(float2*)&spar_h[w*512 + i0]       = make_float2(ch[nf][0], ch[nf][1]);
                *(float2*)&spar_h[w*512 + i0 + 128] = make_float2(ch[nf][2], ch[nf][3]);
            }
        }
        __syncthreads();                       // spar_z/spar_h store -> read
        {
            float sz = gxZ, s = gxH;
            #pragma unroll
            for (int w2 = 0; w2 < NW; w2++) {
                sz += spar_z[w2*512 + tid];
                s  += spar_h[w2*512 + tid];
            }
            const float z  = sigm(sz);
            const float hh = sigm(s);
            const float hn = fmaf(z, hh - hprev, hprev);
            // reference reshape: flat output memory layout is (T,B,D)
            out[(size_t)t*(B_*D_) + rb*D_ + rj] = hn;
            hprev = hn;
            const uint32_t v = (uint32_t)__bfloat16_as_ushort(__float2bfloat16(hn));
            const uint32_t p = __shfl_xor_sync(0xFFFFFFFFu, v, 1);
            if (packer) *hW = v | (p << 16);
        }
        __syncwarp();
        if (lane == 0) red_add_rel(&g_flagH[cta*32], 1u);
    }

    // ---- cleanup: quiesce, then zero own counters so graph replays restart
    grid_barrier(grp);
    if (tid == 0) {
        st_rlx(&g_flagH[cta*32], 0u);
        st_rlx(&g_flagR[cta*32], 0u);
    }
}

// ===================== launch =====================
extern "C" void kernel_launch(void* const* d_in, const int* in_sizes, int n_in,
                              void* d_out, int out_size)
{
    (void)in_sizes; (void)n_in; (void)out_size;
    const float* x  = (const float*)d_in[0];
    const float* Wz = (const float*)d_in[1];
    const float* bz = (const float*)d_in[2];
    const float* Uz = (const float*)d_in[3];
    const float* cz = (const float*)d_in[4];
    const float* Wr = (const float*)d_in[5];
    const float* br = (const float*)d_in[6];
    const float* Ur = (const float*)d_in[7];
    const float* cr = (const float*)d_in[8];
    const float* Wh = (const float*)d_in[9];
    const float* bh = (const float*)d_in[10];
    const float* Uh = (const float*)d_in[11];
    const float* ch = (const float*)d_in[12];
    float* out = (float*)d_out;

    // 1) fused bf16 hi/lo split (W, U, x)
    split_all<<<2048, 256>>>(Wz, Wr, Wh, Uz, Ur, Uh, x);

    // 2) mma.sync GEMM -> g_gx (+bias)
    cudaFuncSetAttribute(gemm_kernel, cudaFuncAttributeMaxDynamicSharedMemorySize,
                         GEMM_SMEM);
    gemm_kernel<<<dim3(32, 24), GM_THREADS, GEMM_SMEM>>>(bz, cz, br, cr, bh, ch);

    // 3) persistent recurrence (z in rh-RT shadow, 1 syncthreads/phase)
    cudaFuncSetAttribute(gru_kernel, cudaFuncAttributeMaxDynamicSharedMemorySize,
                         GRU_SMEM);
    gru_kernel<<<NCTA, TPB, GRU_SMEM>>>(out);
}